// round 1
// baseline (speedup 1.0000x reference)
#include <cuda_runtime.h>
#include <math.h>

// Problem constants
#define U_N   100000
#define B_N   50000
#define NN    150000      // U_N + B_N
#define E_UB  800000
#define E_BB  600000
#define P_N   400000
#define DU    64
#define DB    128
#define H     128

// ---------------- device scratch (static, no runtime alloc) ----------------
__device__ int   g_deg[NN];
__device__ int   g_off[NN];
__device__ int   g_cur[NN];
__device__ int   g_adj[2 * E_UB];
__device__ int   g_degb[B_N];
__device__ int   g_offb[B_N];
__device__ int   g_curb[B_N];
__device__ int   g_adjb[E_BB];
__device__ int   g_bsums[1024];
__device__ float g_dinv[NN];
__device__ float g_acc[(size_t)NN * H];     // x0 -> running acc -> xf (=acc/3)
__device__ float g_ya[(size_t)NN * H];      // y ping
__device__ float g_yb[(size_t)NN * H];      // y pong
__device__ float g_ha[(size_t)B_N * H];     // SAGE h (ping) / book_content
__device__ float g_hb[(size_t)B_N * H];     // SAGE h (pong)
__device__ float g_agg[(size_t)B_N * H];
__device__ float g_relu[(size_t)B_N * H];
__device__ float g_fused[(size_t)B_N * H];

// ---------------- small utility kernels ----------------
__global__ void k_zero() {
    int i = blockIdx.x * blockDim.x + threadIdx.x;
    if (i < NN) { g_deg[i] = 0; g_cur[i] = 0; }
    if (i < B_N) { g_degb[i] = 0; g_curb[i] = 0; }
}

__global__ void k_deg_ub(const int* __restrict__ src, const int* __restrict__ dst) {
    int e = blockIdx.x * blockDim.x + threadIdx.x;
    if (e >= E_UB) return;
    atomicAdd(&g_deg[src[e]], 1);
    atomicAdd(&g_deg[U_N + dst[e]], 1);
}

__global__ void k_deg_bb(const int* __restrict__ dst) {
    int e = blockIdx.x * blockDim.x + threadIdx.x;
    if (e >= E_BB) return;
    atomicAdd(&g_degb[dst[e]], 1);
}

// ---- 3-phase exclusive scan (n <= 1024*1024) ----
__global__ void k_blocksum(const int* __restrict__ in, int n, int* __restrict__ bs) {
    __shared__ int sh[1024];
    int t = threadIdx.x, i = blockIdx.x * 1024 + t;
    sh[t] = (i < n) ? in[i] : 0;
    __syncthreads();
    for (int s = 512; s > 0; s >>= 1) {
        if (t < s) sh[t] += sh[t + s];
        __syncthreads();
    }
    if (t == 0) bs[blockIdx.x] = sh[0];
}

__global__ void k_scan_small(int* bs, int nb) {   // exclusive, single block, nb<=1024
    __shared__ int sh[1024];
    int t = threadIdx.x;
    sh[t] = (t < nb) ? bs[t] : 0;
    __syncthreads();
    for (int o = 1; o < 1024; o <<= 1) {
        int v = (t >= o) ? sh[t - o] : 0;
        __syncthreads();
        sh[t] += v;
        __syncthreads();
    }
    if (t < nb) bs[t] = t ? sh[t - 1] : 0;
}

__global__ void k_scan_block(const int* __restrict__ in, int n,
                             const int* __restrict__ bs, int* __restrict__ out) {
    __shared__ int sh[1024];
    int t = threadIdx.x, i = blockIdx.x * 1024 + t;
    sh[t] = (i < n) ? in[i] : 0;
    __syncthreads();
    for (int o = 1; o < 1024; o <<= 1) {
        int v = (t >= o) ? sh[t - o] : 0;
        __syncthreads();
        sh[t] += v;
        __syncthreads();
    }
    if (i < n) out[i] = (t ? sh[t - 1] : 0) + bs[blockIdx.x];
}

__global__ void k_fill_ub(const int* __restrict__ src, const int* __restrict__ dst) {
    int e = blockIdx.x * blockDim.x + threadIdx.x;
    if (e >= E_UB) return;
    int u = src[e], b = U_N + dst[e];
    int p = atomicAdd(&g_cur[u], 1);
    g_adj[g_off[u] + p] = b;
    int q = atomicAdd(&g_cur[b], 1);
    g_adj[g_off[b] + q] = u;
}

__global__ void k_fill_bb(const int* __restrict__ src, const int* __restrict__ dst) {
    int e = blockIdx.x * blockDim.x + threadIdx.x;
    if (e >= E_BB) return;
    int d = dst[e];
    int p = atomicAdd(&g_curb[d], 1);
    g_adjb[g_offb[d] + p] = src[e];
}

__global__ void k_dinv() {
    int i = blockIdx.x * blockDim.x + threadIdx.x;
    if (i >= NN) return;
    int d = g_deg[i];
    g_dinv[i] = (d > 0) ? rsqrtf((float)d) : 0.0f;
}

// ---------------- SGEMM: C[M x 128] = A[M x K] @ W[K x 128] (+bias)(+C)(relu) --------
#define GF_ACC  1
#define GF_RELU 2

__global__ __launch_bounds__(256)
void k_gemm128(const float* __restrict__ A, const float* __restrict__ W,
               const float* __restrict__ bias, float* __restrict__ C,
               int M, int K, int flags) {
    __shared__ float As[16][128];
    __shared__ float Bs[16][128];
    int tid = threadIdx.x;
    int m0 = blockIdx.x * 128;
    int tm = (tid >> 4) << 3;   // 0..120 step 8
    int tn = (tid & 15) << 3;   // 0..120 step 8

    float acc[8][8];
#pragma unroll
    for (int i = 0; i < 8; i++)
#pragma unroll
        for (int j = 0; j < 8; j++) acc[i][j] = 0.0f;

    for (int k0 = 0; k0 < K; k0 += 16) {
        // A tile: 128 rows x 16 k  (transposed store)
#pragma unroll
        for (int l = 0; l < 2; l++) {
            int id = tid + (l << 8);          // 0..511
            int row = id >> 2;
            int kq = (id & 3) << 2;
            int m = m0 + row;
            float4 v = make_float4(0.f, 0.f, 0.f, 0.f);
            if (m < M) v = *(const float4*)(A + (size_t)m * K + k0 + kq);
            As[kq + 0][row] = v.x;
            As[kq + 1][row] = v.y;
            As[kq + 2][row] = v.z;
            As[kq + 3][row] = v.w;
        }
        // B tile: 16 k x 128 cols
#pragma unroll
        for (int l = 0; l < 2; l++) {
            int id = tid + (l << 8);
            int kr = id >> 5;
            int c4 = (id & 31) << 2;
            *(float4*)&Bs[kr][c4] = *(const float4*)(W + (size_t)(k0 + kr) * H + c4);
        }
        __syncthreads();
#pragma unroll
        for (int kk = 0; kk < 16; kk++) {
            float4 a0 = *(float4*)&As[kk][tm];
            float4 a1 = *(float4*)&As[kk][tm + 4];
            float4 b0 = *(float4*)&Bs[kk][tn];
            float4 b1 = *(float4*)&Bs[kk][tn + 4];
            float af[8] = {a0.x, a0.y, a0.z, a0.w, a1.x, a1.y, a1.z, a1.w};
            float bf[8] = {b0.x, b0.y, b0.z, b0.w, b1.x, b1.y, b1.z, b1.w};
#pragma unroll
            for (int i = 0; i < 8; i++)
#pragma unroll
                for (int j = 0; j < 8; j++) acc[i][j] += af[i] * bf[j];
        }
        __syncthreads();
    }

    float4 bc0 = make_float4(0.f, 0.f, 0.f, 0.f), bc1 = bc0;
    if (bias) {
        bc0 = *(const float4*)(bias + tn);
        bc1 = *(const float4*)(bias + tn + 4);
    }
#pragma unroll
    for (int i = 0; i < 8; i++) {
        int m = m0 + tm + i;
        if (m >= M) continue;
        float* crow = C + (size_t)m * H + tn;
        float4 v0 = make_float4(acc[i][0] + bc0.x, acc[i][1] + bc0.y,
                                acc[i][2] + bc0.z, acc[i][3] + bc0.w);
        float4 v1 = make_float4(acc[i][4] + bc1.x, acc[i][5] + bc1.y,
                                acc[i][6] + bc1.z, acc[i][7] + bc1.w);
        if (flags & GF_ACC) {
            float4 o0 = *(float4*)crow;
            float4 o1 = *(float4*)(crow + 4);
            v0.x += o0.x; v0.y += o0.y; v0.z += o0.z; v0.w += o0.w;
            v1.x += o1.x; v1.y += o1.y; v1.z += o1.z; v1.w += o1.w;
        }
        if (flags & GF_RELU) {
            v0.x = fmaxf(v0.x, 0.f); v0.y = fmaxf(v0.y, 0.f);
            v0.z = fmaxf(v0.z, 0.f); v0.w = fmaxf(v0.w, 0.f);
            v1.x = fmaxf(v1.x, 0.f); v1.y = fmaxf(v1.y, 0.f);
            v1.z = fmaxf(v1.z, 0.f); v1.w = fmaxf(v1.w, 0.f);
        }
        *(float4*)crow = v0;
        *(float4*)(crow + 4) = v1;
    }
}

// ---------------- GCN propagation ----------------
__global__ void k_inity() {          // ya = acc * dinv[row]
    int i = blockIdx.x * blockDim.x + threadIdx.x;   // float4 units
    if (i >= NN * 32) return;
    int row = i >> 5;
    float d = g_dinv[row];
    float4 v = ((const float4*)g_acc)[i];
    v.x *= d; v.y *= d; v.z *= d; v.w *= d;
    ((float4*)g_ya)[i] = v;
}

__global__ void k_spmv_ub(int dir) {
    const float4* y = (const float4*)(dir ? g_yb : g_ya);
    float4* yn = (float4*)(dir ? g_ya : g_yb);
    int w = (blockIdx.x * blockDim.x + threadIdx.x) >> 5;
    int lane = threadIdx.x & 31;
    if (w >= NN) return;
    int start = g_off[w], d = g_deg[w];
    float4 s = make_float4(0.f, 0.f, 0.f, 0.f);
    for (int base = 0; base < d; base += 32) {
        int e = base + lane;
        int nb = (e < d) ? g_adj[start + e] : 0;
        int cnt = min(32, d - base);
        for (int j = 0; j < cnt; j++) {
            int nbj = __shfl_sync(0xffffffffu, nb, j);
            float4 v = y[(size_t)nbj * 32 + lane];
            s.x += v.x; s.y += v.y; s.z += v.z; s.w += v.w;
        }
    }
    float di = g_dinv[w];
    size_t o = (size_t)w * 32 + lane;
    float4 a = ((float4*)g_acc)[o];
    a.x += di * s.x; a.y += di * s.y; a.z += di * s.z; a.w += di * s.w;
    ((float4*)g_acc)[o] = a;
    float dd = di * di;
    yn[o] = make_float4(dd * s.x, dd * s.y, dd * s.z, dd * s.w);
}

__global__ void k_scale_acc() {      // acc *= 1/3 -> xf
    int i = blockIdx.x * blockDim.x + threadIdx.x;
    if (i >= NN * 32) return;
    float4 v = ((const float4*)g_acc)[i];
    const float c = 1.0f / 3.0f;
    v.x *= c; v.y *= c; v.z *= c; v.w *= c;
    ((float4*)g_acc)[i] = v;
}

// ---------------- SAGE mean aggregation ----------------
__global__ void k_spmv_bb(int dir) { // dir 0: read g_ha, 1: read g_hb -> g_agg
    const float4* h = (const float4*)(dir ? g_hb : g_ha);
    int w = (blockIdx.x * blockDim.x + threadIdx.x) >> 5;
    int lane = threadIdx.x & 31;
    if (w >= B_N) return;
    int start = g_offb[w], d = g_degb[w];
    float4 s = make_float4(0.f, 0.f, 0.f, 0.f);
    for (int base = 0; base < d; base += 32) {
        int e = base + lane;
        int nb = (e < d) ? g_adjb[start + e] : 0;
        int cnt = min(32, d - base);
        for (int j = 0; j < cnt; j++) {
            int nbj = __shfl_sync(0xffffffffu, nb, j);
            float4 v = h[(size_t)nbj * 32 + lane];
            s.x += v.x; s.y += v.y; s.z += v.z; s.w += v.w;
        }
    }
    float inv = 1.0f / (float)max(d, 1);
    ((float4*)g_agg)[(size_t)w * 32 + lane] =
        make_float4(inv * s.x, inv * s.y, inv * s.z, inv * s.w);
}

// ---------------- attention fusion ----------------
__global__ void k_fuse(const float* __restrict__ Wf2, const float* __restrict__ bf2) {
    int w = (blockIdx.x * blockDim.x + threadIdx.x) >> 5;
    int lane = threadIdx.x & 31;
    if (w >= B_N) return;
    size_t o = (size_t)w * 32 + lane;
    float4 r = ((const float4*)g_relu)[o];
    // Wf2 is (128,2) row-major: (j,c) at 2*j+c; lane covers j = lane*4..lane*4+3
    const float* w2 = Wf2 + 8 * lane;
    float z0 = r.x * w2[0] + r.y * w2[2] + r.z * w2[4] + r.w * w2[6];
    float z1 = r.x * w2[1] + r.y * w2[3] + r.z * w2[5] + r.w * w2[7];
#pragma unroll
    for (int s = 16; s > 0; s >>= 1) {
        z0 += __shfl_xor_sync(0xffffffffu, z0, s);
        z1 += __shfl_xor_sync(0xffffffffu, z1, s);
    }
    z0 += bf2[0]; z1 += bf2[1];
    float m = fmaxf(z0, z1);
    float e0 = expf(z0 - m), e1 = expf(z1 - m);
    float inv = 1.0f / (e0 + e1);
    float a0 = e0 * inv, a1 = e1 * inv;
    float4 cb = ((const float4*)g_acc)[(size_t)(U_N + w) * 32 + lane];  // collab (already /3)
    float4 ct = ((const float4*)g_ha)[o];                               // content
    ((float4*)g_fused)[o] = make_float4(a0 * cb.x + a1 * ct.x,
                                        a0 * cb.y + a1 * ct.y,
                                        a0 * cb.z + a1 * ct.z,
                                        a0 * cb.w + a1 * ct.w);
}

// ---------------- final scoring ----------------
__global__ void k_score(const int* __restrict__ pu, const int* __restrict__ pb,
                        float* __restrict__ out) {
    int w = (blockIdx.x * blockDim.x + threadIdx.x) >> 5;
    int lane = threadIdx.x & 31;
    if (w >= P_N) return;
    int u = pu[w], b = pb[w];
    float4 a = ((const float4*)g_acc)[(size_t)u * 32 + lane];
    float4 f = ((const float4*)g_fused)[(size_t)b * 32 + lane];
    float s = a.x * f.x + a.y * f.y + a.z * f.z + a.w * f.w;
#pragma unroll
    for (int o = 16; o > 0; o >>= 1) s += __shfl_xor_sync(0xffffffffu, s, o);
    if (lane == 0) out[w] = s;
}

// ---------------- host ----------------
extern "C" void kernel_launch(void* const* d_in, const int* in_sizes, int n_in,
                              void* d_out, int out_size) {
    const float* user_x = (const float*)d_in[0];
    const float* book_x = (const float*)d_in[1];
    const int* ub_src = (const int*)d_in[2];
    const int* ub_dst = (const int*)d_in[3];
    const int* bb_src = (const int*)d_in[4];
    const int* bb_dst = (const int*)d_in[5];
    const int* pred_u = (const int*)d_in[6];
    const int* pred_b = (const int*)d_in[7];
    const float* Wu  = (const float*)d_in[8];
    const float* bu  = (const float*)d_in[9];
    const float* Wub = (const float*)d_in[10];
    const float* bub = (const float*)d_in[11];
    const float* Wbb = (const float*)d_in[12];
    const float* bbb = (const float*)d_in[13];
    const float* Wl1 = (const float*)d_in[14];
    const float* bl1 = (const float*)d_in[15];
    const float* Wr1 = (const float*)d_in[16];
    const float* Wl2 = (const float*)d_in[17];
    const float* bl2 = (const float*)d_in[18];
    const float* Wr2 = (const float*)d_in[19];
    const float* Wf1 = (const float*)d_in[20];
    const float* bf1 = (const float*)d_in[21];
    const float* Wf2 = (const float*)d_in[22];
    const float* bf2 = (const float*)d_in[23];
    float* out = (float*)d_out;

    // device-global addresses for pointer-arg kernels (not a stream op; capture-safe)
    void *p_acc, *p_ha, *p_hb, *p_agg, *p_relu, *p_deg, *p_degb, *p_off, *p_offb, *p_bs;
    cudaGetSymbolAddress(&p_acc, g_acc);
    cudaGetSymbolAddress(&p_ha, g_ha);
    cudaGetSymbolAddress(&p_hb, g_hb);
    cudaGetSymbolAddress(&p_agg, g_agg);
    cudaGetSymbolAddress(&p_relu, g_relu);
    cudaGetSymbolAddress(&p_deg, g_deg);
    cudaGetSymbolAddress(&p_degb, g_degb);
    cudaGetSymbolAddress(&p_off, g_off);
    cudaGetSymbolAddress(&p_offb, g_offb);
    cudaGetSymbolAddress(&p_bs, g_bsums);
    float* acc = (float*)p_acc;
    float* ha = (float*)p_ha;
    float* hb = (float*)p_hb;
    float* agg = (float*)p_agg;
    float* relu = (float*)p_relu;
    int* dg = (int*)p_deg;
    int* dgb = (int*)p_degb;
    int* off = (int*)p_off;
    int* offb = (int*)p_offb;
    int* bs = (int*)p_bs;

    const int TB = 256;
    const int NB_N = (NN + TB - 1) / TB;
    const int NB_EUB = (E_UB + TB - 1) / TB;
    const int NB_EBB = (E_BB + TB - 1) / TB;
    const int SCAN_N = (NN + 1023) / 1024;   // 147
    const int SCAN_B = (B_N + 1023) / 1024;  // 49

    // --- graph structure build ---
    k_zero<<<NB_N, TB>>>();
    k_deg_ub<<<NB_EUB, TB>>>(ub_src, ub_dst);
    k_deg_bb<<<NB_EBB, TB>>>(bb_dst);

    k_blocksum<<<SCAN_N, 1024>>>(dg, NN, bs);
    k_scan_small<<<1, 1024>>>(bs, SCAN_N);
    k_scan_block<<<SCAN_N, 1024>>>(dg, NN, bs, off);
    k_fill_ub<<<NB_EUB, TB>>>(ub_src, ub_dst);

    k_blocksum<<<SCAN_B, 1024>>>(dgb, B_N, bs);
    k_scan_small<<<1, 1024>>>(bs, SCAN_B);
    k_scan_block<<<SCAN_B, 1024>>>(dgb, B_N, bs, offb);
    k_fill_bb<<<NB_EBB, TB>>>(bb_src, bb_dst);

    k_dinv<<<NB_N, TB>>>();

    // --- projections: x0 into g_acc ---
    k_gemm128<<<(U_N + 127) / 128, 256>>>(user_x, Wu, bu, acc, U_N, DU, 0);
    k_gemm128<<<(B_N + 127) / 128, 256>>>(book_x, Wub, bub, acc + (size_t)U_N * H, B_N, DB, 0);

    // --- LightGCN: 2 rounds ---
    const int NB_NH4 = (NN * 32 + TB - 1) / TB;
    k_inity<<<NB_NH4, TB>>>();
    k_spmv_ub<<<(NN * 32 + TB - 1) / TB, TB>>>(0);
    k_spmv_ub<<<(NN * 32 + TB - 1) / TB, TB>>>(1);
    k_scale_acc<<<NB_NH4, TB>>>();

    // --- SAGE over book-book graph ---
    const int GB = (B_N + 127) / 128;
    const int NB_BW = (B_N * 32 + TB - 1) / TB;
    k_gemm128<<<GB, 256>>>(book_x, Wbb, bbb, ha, B_N, DB, 0);

    k_spmv_bb<<<NB_BW, TB>>>(0);                                  // agg from ha
    k_gemm128<<<GB, 256>>>(agg, Wl1, bl1, hb, B_N, H, 0);
    k_gemm128<<<GB, 256>>>(ha, Wr1, nullptr, hb, B_N, H, GF_ACC | GF_RELU);

    k_spmv_bb<<<NB_BW, TB>>>(1);                                  // agg from hb
    k_gemm128<<<GB, 256>>>(agg, Wl2, bl2, ha, B_N, H, 0);
    k_gemm128<<<GB, 256>>>(hb, Wr2, nullptr, ha, B_N, H, GF_ACC | GF_RELU);
    // book_content = ha

    // --- attention fusion ---
    k_gemm128<<<GB, 256>>>(acc + (size_t)U_N * H, Wf1, bf1, relu, B_N, H, 0);
    k_gemm128<<<GB, 256>>>(ha, Wf1 + (size_t)H * H, nullptr, relu, B_N, H, GF_ACC | GF_RELU);
    k_fuse<<<NB_BW, TB>>>(Wf2, bf2);

    // --- scoring ---
    k_score<<<(P_N * 32 + TB - 1) / TB, TB>>>(pred_u, pred_b, out);
}

// round 3
// speedup vs baseline: 1.2777x; 1.2777x over previous
#include <cuda_runtime.h>
#include <cuda_bf16.h>
#include <cstdint>
#include <math.h>

// Problem constants
#define U_N   100000
#define B_N   50000
#define NN    150000      // U_N + B_N
#define E_UB  800000
#define E_BB  600000
#define P_N   400000
#define DU    64
#define DB    128
#define H     128

// ---------------- device scratch (static, no runtime alloc) ----------------
__device__ int   g_deg[NN];
__device__ int   g_off[NN];
__device__ int   g_cur[NN];
__device__ int   g_adj[2 * E_UB];
__device__ int   g_degb[B_N];
__device__ int   g_offb[B_N];
__device__ int   g_curb[B_N];
__device__ int   g_adjb[E_BB];
__device__ int   g_bsums[1024];
__device__ float g_dinv[NN];
__device__ float g_acc[(size_t)NN * H];     // x0 -> running acc (xf = acc/3, folded downstream)
__device__ float g_ya[(size_t)NN * H];      // y ping
__device__ float g_yb[(size_t)NN * H];      // y pong
__device__ float g_ha[(size_t)B_N * H];     // SAGE h (ping) / book_content
__device__ float g_hb[(size_t)B_N * H];     // SAGE h (pong)
__device__ float g_agg[(size_t)B_N * H];
__device__ float g_relu[(size_t)B_N * H];
__device__ float g_fused[(size_t)B_N * H];

// ---------------- small utility kernels ----------------
__global__ void k_zero() {
    int i = blockIdx.x * blockDim.x + threadIdx.x;
    if (i < NN) { g_deg[i] = 0; g_cur[i] = 0; }
    if (i < B_N) { g_degb[i] = 0; g_curb[i] = 0; }
}

__global__ void k_deg_ub(const int* __restrict__ src, const int* __restrict__ dst) {
    int e = blockIdx.x * blockDim.x + threadIdx.x;
    if (e >= E_UB) return;
    atomicAdd(&g_deg[src[e]], 1);
    atomicAdd(&g_deg[U_N + dst[e]], 1);
}

__global__ void k_deg_bb(const int* __restrict__ dst) {
    int e = blockIdx.x * blockDim.x + threadIdx.x;
    if (e >= E_BB) return;
    atomicAdd(&g_degb[dst[e]], 1);
}

// ---- 3-phase exclusive scan ----
__global__ void k_blocksum(const int* __restrict__ in, int n, int* __restrict__ bs) {
    __shared__ int sh[1024];
    int t = threadIdx.x, i = blockIdx.x * 1024 + t;
    sh[t] = (i < n) ? in[i] : 0;
    __syncthreads();
    for (int s = 512; s > 0; s >>= 1) {
        if (t < s) sh[t] += sh[t + s];
        __syncthreads();
    }
    if (t == 0) bs[blockIdx.x] = sh[0];
}

__global__ void k_scan_small(int* bs, int nb) {
    __shared__ int sh[1024];
    int t = threadIdx.x;
    sh[t] = (t < nb) ? bs[t] : 0;
    __syncthreads();
    for (int o = 1; o < 1024; o <<= 1) {
        int v = (t >= o) ? sh[t - o] : 0;
        __syncthreads();
        sh[t] += v;
        __syncthreads();
    }
    if (t < nb) bs[t] = t ? sh[t - 1] : 0;
}

__global__ void k_scan_block(const int* __restrict__ in, int n,
                             const int* __restrict__ bs, int* __restrict__ out) {
    __shared__ int sh[1024];
    int t = threadIdx.x, i = blockIdx.x * 1024 + t;
    sh[t] = (i < n) ? in[i] : 0;
    __syncthreads();
    for (int o = 1; o < 1024; o <<= 1) {
        int v = (t >= o) ? sh[t - o] : 0;
        __syncthreads();
        sh[t] += v;
        __syncthreads();
    }
    if (i < n) out[i] = (t ? sh[t - 1] : 0) + bs[blockIdx.x];
}

__global__ void k_fill_ub(const int* __restrict__ src, const int* __restrict__ dst) {
    int e = blockIdx.x * blockDim.x + threadIdx.x;
    if (e >= E_UB) return;
    int u = src[e], b = U_N + dst[e];
    int p = atomicAdd(&g_cur[u], 1);
    g_adj[g_off[u] + p] = b;
    int q = atomicAdd(&g_cur[b], 1);
    g_adj[g_off[b] + q] = u;
}

__global__ void k_fill_bb(const int* __restrict__ src, const int* __restrict__ dst) {
    int e = blockIdx.x * blockDim.x + threadIdx.x;
    if (e >= E_BB) return;
    int d = dst[e];
    int p = atomicAdd(&g_curb[d], 1);
    g_adjb[g_offb[d] + p] = src[e];
}

__global__ void k_dinv() {
    int i = blockIdx.x * blockDim.x + threadIdx.x;
    if (i >= NN) return;
    int d = g_deg[i];
    g_dinv[i] = (d > 0) ? rsqrtf((float)d) : 0.0f;
}

// ---------------- bf16 split-3 HMMA GEMM: C[M x 128] = alpha*A[M x K]@W[K x 128] ----
#define GF_ACC    1
#define GF_RELU   2
#define GF_WRITEY 4

#define MMA_BF16(d, a, b) \
    asm volatile("mma.sync.aligned.m16n8k16.row.col.f32.bf16.bf16.f32 " \
                 "{%0,%1,%2,%3}, {%4,%5,%6,%7}, {%8,%9}, {%0,%1,%2,%3};" \
                 : "+f"((d)[0]), "+f"((d)[1]), "+f"((d)[2]), "+f"((d)[3]) \
                 : "r"((a)[0]), "r"((a)[1]), "r"((a)[2]), "r"((a)[3]), \
                   "r"((b)[0]), "r"((b)[1]))

__global__ __launch_bounds__(256, 2)
void k_gemm_mma(const float* __restrict__ A, const float* __restrict__ W,
                const float* __restrict__ bias, float* __restrict__ C,
                int M, int K, int flags, float alpha,
                float* __restrict__ Y, const float* __restrict__ dinv) {
    __shared__ __nv_bfloat16 Ah[128][36];
    __shared__ __nv_bfloat16 Al[128][36];
    __shared__ __nv_bfloat16 Bh[128][34];
    __shared__ __nv_bfloat16 Bl[128][34];

    const int tid = threadIdx.x;
    const int lane = tid & 31;
    const int wid = tid >> 5;
    const int g = lane >> 2;        // 0..7
    const int t = lane & 3;         // 0..3
    const int wm = wid >> 2;        // 0..1  (64-row slab)
    const int wn = wid & 3;         // 0..3  (32-col slab)
    const int m0 = blockIdx.x * 128;

    float acc[4][4][4];
#pragma unroll
    for (int i = 0; i < 4; i++)
#pragma unroll
        for (int j = 0; j < 4; j++) {
            acc[i][j][0] = 0.f; acc[i][j][1] = 0.f;
            acc[i][j][2] = 0.f; acc[i][j][3] = 0.f;
        }

    for (int k0 = 0; k0 < K; k0 += 32) {
        // stage A: 128 rows x 32 k, fp32 -> bf16 hi/lo
#pragma unroll
        for (int i = 0; i < 4; i++) {
            int idx = tid + (i << 8);       // 0..1023
            int row = idx >> 3;             // 8 float4 per row
            int c4 = (idx & 7) << 2;
            int m = m0 + row;
            float4 v = make_float4(0.f, 0.f, 0.f, 0.f);
            if (m < M) v = *(const float4*)(A + (size_t)m * K + k0 + c4);
            float vv[4] = {v.x, v.y, v.z, v.w};
#pragma unroll
            for (int j = 0; j < 4; j++) {
                __nv_bfloat16 h = __float2bfloat16_rn(vv[j]);
                __nv_bfloat16 l = __float2bfloat16_rn(vv[j] - __bfloat162float(h));
                Ah[row][c4 + j] = h;
                Al[row][c4 + j] = l;
            }
        }
        // stage B: W rows k0..k0+31 x 128 cols -> Bs[n][k] (col-major B for mma)
#pragma unroll
        for (int i = 0; i < 4; i++) {
            int idx = tid + (i << 8);
            int k = idx >> 5;               // 0..31
            int n4 = (idx & 31) << 2;
            float4 v = *(const float4*)(W + (size_t)(k0 + k) * H + n4);
            float vv[4] = {v.x, v.y, v.z, v.w};
#pragma unroll
            for (int j = 0; j < 4; j++) {
                __nv_bfloat16 h = __float2bfloat16_rn(vv[j]);
                __nv_bfloat16 l = __float2bfloat16_rn(vv[j] - __bfloat162float(h));
                Bh[n4 + j][k] = h;
                Bl[n4 + j][k] = l;
            }
        }
        __syncthreads();

#pragma unroll
        for (int ks = 0; ks < 2; ks++) {
            const int kk = (ks << 4) + 2 * t;
            uint32_t bh[4][2], bl[4][2];
#pragma unroll
            for (int nf = 0; nf < 4; nf++) {
                int n = (wn << 5) + (nf << 3) + g;
                bh[nf][0] = *(const uint32_t*)&Bh[n][kk];
                bh[nf][1] = *(const uint32_t*)&Bh[n][kk + 8];
                bl[nf][0] = *(const uint32_t*)&Bl[n][kk];
                bl[nf][1] = *(const uint32_t*)&Bl[n][kk + 8];
            }
#pragma unroll
            for (int mf = 0; mf < 4; mf++) {
                int r = (wm << 6) + (mf << 4) + g;
                uint32_t ah[4], al[4];
                ah[0] = *(const uint32_t*)&Ah[r][kk];
                ah[1] = *(const uint32_t*)&Ah[r + 8][kk];
                ah[2] = *(const uint32_t*)&Ah[r][kk + 8];
                ah[3] = *(const uint32_t*)&Ah[r + 8][kk + 8];
                al[0] = *(const uint32_t*)&Al[r][kk];
                al[1] = *(const uint32_t*)&Al[r + 8][kk];
                al[2] = *(const uint32_t*)&Al[r][kk + 8];
                al[3] = *(const uint32_t*)&Al[r + 8][kk + 8];
#pragma unroll
                for (int nf = 0; nf < 4; nf++) {
                    MMA_BF16(acc[mf][nf], ah, bh[nf]);
                    MMA_BF16(acc[mf][nf], ah, bl[nf]);
                    MMA_BF16(acc[mf][nf], al, bh[nf]);
                }
            }
        }
        __syncthreads();
    }

    // epilogue: c0,c1 = (row g, cols 2t,2t+1); c2,c3 = (row g+8)
#pragma unroll
    for (int mf = 0; mf < 4; mf++) {
#pragma unroll
        for (int half = 0; half < 2; half++) {
            int r = m0 + (wm << 6) + (mf << 4) + g + half * 8;
            if (r >= M) continue;
            float dv = (flags & GF_WRITEY) ? dinv[r] : 0.f;
#pragma unroll
            for (int nf = 0; nf < 4; nf++) {
                int c = (wn << 5) + (nf << 3) + 2 * t;
                float v0 = alpha * acc[mf][nf][half * 2 + 0];
                float v1 = alpha * acc[mf][nf][half * 2 + 1];
                if (bias) { v0 += __ldg(bias + c); v1 += __ldg(bias + c + 1); }
                float* cp = C + (size_t)r * H + c;
                if (flags & GF_ACC) {
                    float2 o = *(const float2*)cp;
                    v0 += o.x; v1 += o.y;
                }
                if (flags & GF_RELU) { v0 = fmaxf(v0, 0.f); v1 = fmaxf(v1, 0.f); }
                *(float2*)cp = make_float2(v0, v1);
                if (flags & GF_WRITEY)
                    *(float2*)(Y + (size_t)r * H + c) = make_float2(dv * v0, dv * v1);
            }
        }
    }
}

// ---------------- GCN propagation ----------------
__global__ void k_spmv_ub(int dir) {
    const float4* y = (const float4*)(dir ? g_yb : g_ya);
    float4* yn = (float4*)(dir ? g_ya : g_yb);
    int w = (blockIdx.x * blockDim.x + threadIdx.x) >> 5;
    int lane = threadIdx.x & 31;
    if (w >= NN) return;
    int start = g_off[w], d = g_deg[w];
    float4 s = make_float4(0.f, 0.f, 0.f, 0.f);
    for (int base = 0; base < d; base += 32) {
        int e = base + lane;
        int nb = (e < d) ? g_adj[start + e] : 0;
        int cnt = min(32, d - base);
        for (int j = 0; j < cnt; j++) {
            int nbj = __shfl_sync(0xffffffffu, nb, j);
            float4 v = y[(size_t)nbj * 32 + lane];
            s.x += v.x; s.y += v.y; s.z += v.z; s.w += v.w;
        }
    }
    float di = g_dinv[w];
    size_t o = (size_t)w * 32 + lane;
    float4 aa = ((float4*)g_acc)[o];
    aa.x += di * s.x; aa.y += di * s.y; aa.z += di * s.z; aa.w += di * s.w;
    ((float4*)g_acc)[o] = aa;
    float dd = di * di;
    yn[o] = make_float4(dd * s.x, dd * s.y, dd * s.z, dd * s.w);
}

// ---------------- SAGE mean aggregation ----------------
__global__ void k_spmv_bb(int dir) {
    const float4* h = (const float4*)(dir ? g_hb : g_ha);
    int w = (blockIdx.x * blockDim.x + threadIdx.x) >> 5;
    int lane = threadIdx.x & 31;
    if (w >= B_N) return;
    int start = g_offb[w], d = g_degb[w];
    float4 s = make_float4(0.f, 0.f, 0.f, 0.f);
    for (int base = 0; base < d; base += 32) {
        int e = base + lane;
        int nb = (e < d) ? g_adjb[start + e] : 0;
        int cnt = min(32, d - base);
        for (int j = 0; j < cnt; j++) {
            int nbj = __shfl_sync(0xffffffffu, nb, j);
            float4 v = h[(size_t)nbj * 32 + lane];
            s.x += v.x; s.y += v.y; s.z += v.z; s.w += v.w;
        }
    }
    float inv = 1.0f / (float)max(d, 1);
    ((float4*)g_agg)[(size_t)w * 32 + lane] =
        make_float4(inv * s.x, inv * s.y, inv * s.z, inv * s.w);
}

// ---------------- attention fusion ----------------
__global__ void k_fuse(const float* __restrict__ Wf2, const float* __restrict__ bf2) {
    int w = (blockIdx.x * blockDim.x + threadIdx.x) >> 5;
    int lane = threadIdx.x & 31;
    if (w >= B_N) return;
    size_t o = (size_t)w * 32 + lane;
    float4 r = ((const float4*)g_relu)[o];
    const float* w2 = Wf2 + 8 * lane;
    float z0 = r.x * w2[0] + r.y * w2[2] + r.z * w2[4] + r.w * w2[6];
    float z1 = r.x * w2[1] + r.y * w2[3] + r.z * w2[5] + r.w * w2[7];
#pragma unroll
    for (int s = 16; s > 0; s >>= 1) {
        z0 += __shfl_xor_sync(0xffffffffu, z0, s);
        z1 += __shfl_xor_sync(0xffffffffu, z1, s);
    }
    z0 += bf2[0]; z1 += bf2[1];
    float m = fmaxf(z0, z1);
    float e0 = expf(z0 - m), e1 = expf(z1 - m);
    float inv = 1.0f / (e0 + e1);
    float a0 = e0 * inv, a1 = e1 * inv;
    const float third = 1.0f / 3.0f;
    float4 cb = ((const float4*)g_acc)[(size_t)(U_N + w) * 32 + lane];  // unscaled acc
    cb.x *= third; cb.y *= third; cb.z *= third; cb.w *= third;        // book_collab
    float4 ct = ((const float4*)g_ha)[o];                              // content
    ((float4*)g_fused)[o] = make_float4(a0 * cb.x + a1 * ct.x,
                                        a0 * cb.y + a1 * ct.y,
                                        a0 * cb.z + a1 * ct.z,
                                        a0 * cb.w + a1 * ct.w);
}

// ---------------- final scoring ----------------
__global__ void k_score(const int* __restrict__ pu, const int* __restrict__ pb,
                        float* __restrict__ out) {
    int w = (blockIdx.x * blockDim.x + threadIdx.x) >> 5;
    int lane = threadIdx.x & 31;
    if (w >= P_N) return;
    int u = pu[w], b = pb[w];
    float4 a = ((const float4*)g_acc)[(size_t)u * 32 + lane];   // unscaled acc
    float4 f = ((const float4*)g_fused)[(size_t)b * 32 + lane];
    float s = a.x * f.x + a.y * f.y + a.z * f.z + a.w * f.w;
#pragma unroll
    for (int o = 16; o > 0; o >>= 1) s += __shfl_xor_sync(0xffffffffu, s, o);
    if (lane == 0) out[w] = s * (1.0f / 3.0f);                  // user_emb = acc/3
}

// ---------------- host ----------------
extern "C" void kernel_launch(void* const* d_in, const int* in_sizes, int n_in,
                              void* d_out, int out_size) {
    const float* user_x = (const float*)d_in[0];
    const float* book_x = (const float*)d_in[1];
    const int* ub_src = (const int*)d_in[2];
    const int* ub_dst = (const int*)d_in[3];
    const int* bb_src = (const int*)d_in[4];
    const int* bb_dst = (const int*)d_in[5];
    const int* pred_u = (const int*)d_in[6];
    const int* pred_b = (const int*)d_in[7];
    const float* Wu  = (const float*)d_in[8];
    const float* bu  = (const float*)d_in[9];
    const float* Wub = (const float*)d_in[10];
    const float* bub = (const float*)d_in[11];
    const float* Wbb = (const float*)d_in[12];
    const float* bbb = (const float*)d_in[13];
    const float* Wl1 = (const float*)d_in[14];
    const float* bl1 = (const float*)d_in[15];
    const float* Wr1 = (const float*)d_in[16];
    const float* Wl2 = (const float*)d_in[17];
    const float* bl2 = (const float*)d_in[18];
    const float* Wr2 = (const float*)d_in[19];
    const float* Wf1 = (const float*)d_in[20];
    const float* bf1 = (const float*)d_in[21];
    const float* Wf2 = (const float*)d_in[22];
    const float* bf2 = (const float*)d_in[23];
    float* out = (float*)d_out;

    void *p_acc, *p_ha, *p_hb, *p_agg, *p_relu, *p_deg, *p_degb, *p_off, *p_offb, *p_bs,
         *p_ya, *p_dinv;
    cudaGetSymbolAddress(&p_acc, g_acc);
    cudaGetSymbolAddress(&p_ha, g_ha);
    cudaGetSymbolAddress(&p_hb, g_hb);
    cudaGetSymbolAddress(&p_agg, g_agg);
    cudaGetSymbolAddress(&p_relu, g_relu);
    cudaGetSymbolAddress(&p_deg, g_deg);
    cudaGetSymbolAddress(&p_degb, g_degb);
    cudaGetSymbolAddress(&p_off, g_off);
    cudaGetSymbolAddress(&p_offb, g_offb);
    cudaGetSymbolAddress(&p_bs, g_bsums);
    cudaGetSymbolAddress(&p_ya, g_ya);
    cudaGetSymbolAddress(&p_dinv, g_dinv);
    float* acc = (float*)p_acc;
    float* ha = (float*)p_ha;
    float* hb = (float*)p_hb;
    float* agg = (float*)p_agg;
    float* relu = (float*)p_relu;
    int* dg = (int*)p_deg;
    int* dgb = (int*)p_degb;
    int* off = (int*)p_off;
    int* offb = (int*)p_offb;
    int* bs = (int*)p_bs;
    float* ya = (float*)p_ya;
    float* dinv = (float*)p_dinv;

    const int TB = 256;
    const int NB_N = (NN + TB - 1) / TB;
    const int NB_EUB = (E_UB + TB - 1) / TB;
    const int NB_EBB = (E_BB + TB - 1) / TB;
    const int SCAN_N = (NN + 1023) / 1024;
    const int SCAN_B = (B_N + 1023) / 1024;

    // --- graph structure build ---
    k_zero<<<NB_N, TB>>>();
    k_deg_ub<<<NB_EUB, TB>>>(ub_src, ub_dst);
    k_deg_bb<<<NB_EBB, TB>>>(bb_dst);

    k_blocksum<<<SCAN_N, 1024>>>(dg, NN, bs);
    k_scan_small<<<1, 1024>>>(bs, SCAN_N);
    k_scan_block<<<SCAN_N, 1024>>>(dg, NN, bs, off);
    k_fill_ub<<<NB_EUB, TB>>>(ub_src, ub_dst);

    k_blocksum<<<SCAN_B, 1024>>>(dgb, B_N, bs);
    k_scan_small<<<1, 1024>>>(bs, SCAN_B);
    k_scan_block<<<SCAN_B, 1024>>>(dgb, B_N, bs, offb);
    k_fill_bb<<<NB_EBB, TB>>>(bb_src, bb_dst);

    k_dinv<<<NB_N, TB>>>();

    // --- projections: x0 into g_acc, y0 = dinv*x0 into g_ya (fused) ---
    const int GU = (U_N + 127) / 128;
    const int GB = (B_N + 127) / 128;
    k_gemm_mma<<<GU, 256>>>(user_x, Wu, bu, acc, U_N, DU,
                            GF_WRITEY, 1.0f, ya, dinv);
    k_gemm_mma<<<GB, 256>>>(book_x, Wub, bub, acc + (size_t)U_N * H, B_N, DB,
                            GF_WRITEY, 1.0f, ya + (size_t)U_N * H, dinv + U_N);

    // --- LightGCN: 2 rounds (acc accumulates; xf = acc/3 folded downstream) ---
    k_spmv_ub<<<(NN * 32 + TB - 1) / TB, TB>>>(0);
    k_spmv_ub<<<(NN * 32 + TB - 1) / TB, TB>>>(1);

    // --- SAGE over book-book graph ---
    const int NB_BW = (B_N * 32 + TB - 1) / TB;
    k_gemm_mma<<<GB, 256>>>(book_x, Wbb, bbb, ha, B_N, DB, 0, 1.0f, nullptr, nullptr);

    k_spmv_bb<<<NB_BW, TB>>>(0);
    k_gemm_mma<<<GB, 256>>>(agg, Wl1, bl1, hb, B_N, H, 0, 1.0f, nullptr, nullptr);
    k_gemm_mma<<<GB, 256>>>(ha, Wr1, nullptr, hb, B_N, H,
                            GF_ACC | GF_RELU, 1.0f, nullptr, nullptr);

    k_spmv_bb<<<NB_BW, TB>>>(1);
    k_gemm_mma<<<GB, 256>>>(agg, Wl2, bl2, ha, B_N, H, 0, 1.0f, nullptr, nullptr);
    k_gemm_mma<<<GB, 256>>>(hb, Wr2, nullptr, ha, B_N, H,
                            GF_ACC | GF_RELU, 1.0f, nullptr, nullptr);
    // book_content = ha

    // --- attention fusion: comb@Wf1 = collab@Wf1[:H] + content@Wf1[H:] ---
    k_gemm_mma<<<GB, 256>>>(acc + (size_t)U_N * H, Wf1, bf1, relu, B_N, H,
                            0, 1.0f / 3.0f, nullptr, nullptr);
    k_gemm_mma<<<GB, 256>>>(ha, Wf1 + (size_t)H * H, nullptr, relu, B_N, H,
                            GF_ACC | GF_RELU, 1.0f, nullptr, nullptr);
    k_fuse<<<NB_BW, TB>>>(Wf2, bf2);

    // --- scoring ---
    k_score<<<(P_N * 32 + TB - 1) / TB, TB>>>(pred_u, pred_b, out);
}

// round 4
// speedup vs baseline: 1.4255x; 1.1156x over previous
#include <cuda_runtime.h>
#include <cuda_bf16.h>
#include <cstdint>
#include <math.h>

// Problem constants
#define U_N   100000
#define B_N   50000
#define NN    150000      // U_N + B_N
#define NA    200000      // NN + B_N  (concatenated degree/offset arrays)
#define E_UB  800000
#define E_BB  600000
#define P_N   400000
#define DU    64
#define DB    128
#define H     128

// ---------------- device scratch (static, no runtime alloc) ----------------
__device__ int   g_degall[NA];   // [0:NN) ub-graph degree, [NN:NA) bb-graph degree
__device__ int   g_offall[NA];   // exclusive scan of g_degall
__device__ int   g_cur[NN];
__device__ int   g_curb[B_N];
__device__ int   g_adj[2 * E_UB];
__device__ int   g_adjb[E_BB];
__device__ int   g_bsums[1024];
__device__ float g_dinv[NN];
__device__ float g_acc[(size_t)NN * H];     // x0 -> running acc (xf = acc/3, folded downstream)
__device__ float g_ya[(size_t)NN * H];      // y ping
__device__ float g_yb[(size_t)NN * H];      // y pong
__device__ float g_ha[(size_t)B_N * H];     // SAGE h (ping) / book_content
__device__ float g_hb[(size_t)B_N * H];     // SAGE h (pong)
__device__ float g_agg[(size_t)B_N * H];
__device__ float g_relu[(size_t)B_N * H];
__device__ float g_fused[(size_t)B_N * H];

// ---------------- graph build ----------------
__global__ void k_zero() {
    int i = blockIdx.x * blockDim.x + threadIdx.x;
    if (i < NA) g_degall[i] = 0;
    if (i < NN) g_cur[i] = 0;
    if (i < B_N) g_curb[i] = 0;
}

__global__ void k_deg(const int* __restrict__ usrc, const int* __restrict__ udst,
                      const int* __restrict__ bdst) {
    int e = blockIdx.x * blockDim.x + threadIdx.x;
    if (e < E_UB) {
        atomicAdd(&g_degall[usrc[e]], 1);
        atomicAdd(&g_degall[U_N + udst[e]], 1);
    }
    if (e < E_BB) atomicAdd(&g_degall[NN + bdst[e]], 1);
}

__global__ void k_blocksum(const int* __restrict__ in, int n, int* __restrict__ bs) {
    __shared__ int sh[1024];
    int t = threadIdx.x, i = blockIdx.x * 1024 + t;
    sh[t] = (i < n) ? in[i] : 0;
    __syncthreads();
    for (int s = 512; s > 0; s >>= 1) {
        if (t < s) sh[t] += sh[t + s];
        __syncthreads();
    }
    if (t == 0) bs[blockIdx.x] = sh[0];
}

__global__ void k_scan_small(int* bs, int nb) {
    __shared__ int sh[1024];
    int t = threadIdx.x;
    sh[t] = (t < nb) ? bs[t] : 0;
    __syncthreads();
    for (int o = 1; o < 1024; o <<= 1) {
        int v = (t >= o) ? sh[t - o] : 0;
        __syncthreads();
        sh[t] += v;
        __syncthreads();
    }
    if (t < nb) bs[t] = t ? sh[t - 1] : 0;
}

// scan + fused dinv computation
__global__ void k_scan_block(const int* __restrict__ in, int n,
                             const int* __restrict__ bs, int* __restrict__ out) {
    __shared__ int sh[1024];
    int t = threadIdx.x, i = blockIdx.x * 1024 + t;
    int d = (i < n) ? in[i] : 0;
    sh[t] = d;
    __syncthreads();
    for (int o = 1; o < 1024; o <<= 1) {
        int v = (t >= o) ? sh[t - o] : 0;
        __syncthreads();
        sh[t] += v;
        __syncthreads();
    }
    if (i < n) {
        out[i] = (t ? sh[t - 1] : 0) + bs[blockIdx.x];
        if (i < NN) g_dinv[i] = (d > 0) ? rsqrtf((float)d) : 0.0f;
    }
}

__global__ void k_fill(const int* __restrict__ usrc, const int* __restrict__ udst,
                       const int* __restrict__ bsrc, const int* __restrict__ bdst) {
    int e = blockIdx.x * blockDim.x + threadIdx.x;
    if (e < E_UB) {
        int u = usrc[e], b = U_N + udst[e];
        int p = atomicAdd(&g_cur[u], 1);
        g_adj[g_offall[u] + p] = b;
        int q = atomicAdd(&g_cur[b], 1);
        g_adj[g_offall[b] + q] = u;
    }
    if (e < E_BB) {
        int d = bdst[e];
        int p = atomicAdd(&g_curb[d], 1);
        g_adjb[g_offall[NN + d] - 2 * E_UB + p] = bsrc[e];
    }
}

// ------- bf16 split-3 HMMA GEMM: C[Mx128] = s1*A1@W1 + A2@W2 (+bias)(relu) -------
#define GF_RELU   2
#define GF_WRITEY 4

#define MMA_BF16(d, a, b) \
    asm volatile("mma.sync.aligned.m16n8k16.row.col.f32.bf16.bf16.f32 " \
                 "{%0,%1,%2,%3}, {%4,%5,%6,%7}, {%8,%9}, {%0,%1,%2,%3};" \
                 : "+f"((d)[0]), "+f"((d)[1]), "+f"((d)[2]), "+f"((d)[3]) \
                 : "r"((a)[0]), "r"((a)[1]), "r"((a)[2]), "r"((a)[3]), \
                   "r"((b)[0]), "r"((b)[1]))

__global__ __launch_bounds__(256)
void k_gemm_mma(const float* __restrict__ A1, const float* __restrict__ W1,
                int K1, float s1,
                const float* __restrict__ A2, const float* __restrict__ W2, int K2,
                const float* __restrict__ bias, float* __restrict__ C,
                int M, int flags,
                float* __restrict__ Y, const float* __restrict__ dinv) {
    __shared__ __nv_bfloat16 Ah[128][36];
    __shared__ __nv_bfloat16 Al[128][36];
    __shared__ __nv_bfloat16 Bh[128][34];
    __shared__ __nv_bfloat16 Bl[128][34];

    const int tid = threadIdx.x;
    const int lane = tid & 31;
    const int wid = tid >> 5;
    const int g = lane >> 2;
    const int t = lane & 3;
    const int wm = wid >> 2;
    const int wn = wid & 3;
    const int m0 = blockIdx.x * 128;
    const int np1 = K1 >> 5;
    const int np = np1 + (K2 >> 5);

    float acc[4][4][4];
#pragma unroll
    for (int i = 0; i < 4; i++)
#pragma unroll
        for (int j = 0; j < 4; j++) {
            acc[i][j][0] = 0.f; acc[i][j][1] = 0.f;
            acc[i][j][2] = 0.f; acc[i][j][3] = 0.f;
        }

    // staging index derivations (constant per thread)
    int arow[4], ac4[4], bk[4], bn4[4];
#pragma unroll
    for (int i = 0; i < 4; i++) {
        int idx = tid + (i << 8);
        arow[i] = idx >> 3;  ac4[i] = (idx & 7) << 2;
        bk[i]   = idx >> 5;  bn4[i] = (idx & 31) << 2;
    }

    float4 av[4], bv[4];
    float scs = 1.0f;

    // prologue: load tile 0
    {
        const float* Ap = np1 ? A1 : A2;
        int Ks = np1 ? K1 : K2;
        const float* Wp = np1 ? W1 : W2;
        scs = np1 ? s1 : 1.0f;
#pragma unroll
        for (int i = 0; i < 4; i++) {
            int m = m0 + arow[i];
            av[i] = make_float4(0.f, 0.f, 0.f, 0.f);
            if (m < M) av[i] = *(const float4*)(Ap + (size_t)m * Ks + ac4[i]);
            bv[i] = *(const float4*)(Wp + (size_t)bk[i] * H + bn4[i]);
        }
    }

    for (int p = 0; p < np; p++) {
        // store staged registers to smem with bf16 hi/lo split (+alpha on A)
#pragma unroll
        for (int i = 0; i < 4; i++) {
            float vv[4] = {scs * av[i].x, scs * av[i].y, scs * av[i].z, scs * av[i].w};
#pragma unroll
            for (int j = 0; j < 4; j++) {
                __nv_bfloat16 h = __float2bfloat16_rn(vv[j]);
                Ah[arow[i]][ac4[i] + j] = h;
                Al[arow[i]][ac4[i] + j] = __float2bfloat16_rn(vv[j] - __bfloat162float(h));
            }
            float ww[4] = {bv[i].x, bv[i].y, bv[i].z, bv[i].w};
#pragma unroll
            for (int j = 0; j < 4; j++) {
                __nv_bfloat16 h = __float2bfloat16_rn(ww[j]);
                Bh[bn4[i] + j][bk[i]] = h;
                Bl[bn4[i] + j][bk[i]] = __float2bfloat16_rn(ww[j] - __bfloat162float(h));
            }
        }
        __syncthreads();

        // prefetch next tile (overlaps with MMA below)
        float nsc = scs;
        if (p + 1 < np) {
            int q = p + 1;
            const float* Ap; const float* Wp; int Ks, kl;
            if (q < np1) { Ap = A1; Wp = W1; Ks = K1; kl = q << 5; nsc = s1; }
            else         { Ap = A2; Wp = W2; Ks = K2; kl = (q - np1) << 5; nsc = 1.0f; }
#pragma unroll
            for (int i = 0; i < 4; i++) {
                int m = m0 + arow[i];
                av[i] = make_float4(0.f, 0.f, 0.f, 0.f);
                if (m < M) av[i] = *(const float4*)(Ap + (size_t)m * Ks + kl + ac4[i]);
                bv[i] = *(const float4*)(Wp + (size_t)(kl + bk[i]) * H + bn4[i]);
            }
        }

#pragma unroll
        for (int ks = 0; ks < 2; ks++) {
            const int kk = (ks << 4) + 2 * t;
            uint32_t bh[4][2], bl[4][2];
#pragma unroll
            for (int nf = 0; nf < 4; nf++) {
                int n = (wn << 5) + (nf << 3) + g;
                bh[nf][0] = *(const uint32_t*)&Bh[n][kk];
                bh[nf][1] = *(const uint32_t*)&Bh[n][kk + 8];
                bl[nf][0] = *(const uint32_t*)&Bl[n][kk];
                bl[nf][1] = *(const uint32_t*)&Bl[n][kk + 8];
            }
#pragma unroll
            for (int mf = 0; mf < 4; mf++) {
                int r = (wm << 6) + (mf << 4) + g;
                uint32_t ah[4], al[4];
                ah[0] = *(const uint32_t*)&Ah[r][kk];
                ah[1] = *(const uint32_t*)&Ah[r + 8][kk];
                ah[2] = *(const uint32_t*)&Ah[r][kk + 8];
                ah[3] = *(const uint32_t*)&Ah[r + 8][kk + 8];
                al[0] = *(const uint32_t*)&Al[r][kk];
                al[1] = *(const uint32_t*)&Al[r + 8][kk];
                al[2] = *(const uint32_t*)&Al[r][kk + 8];
                al[3] = *(const uint32_t*)&Al[r + 8][kk + 8];
#pragma unroll
                for (int nf = 0; nf < 4; nf++) {
                    MMA_BF16(acc[mf][nf], ah, bh[nf]);
                    MMA_BF16(acc[mf][nf], ah, bl[nf]);
                    MMA_BF16(acc[mf][nf], al, bh[nf]);
                }
            }
        }
        __syncthreads();
        scs = nsc;
    }

    // epilogue
#pragma unroll
    for (int mf = 0; mf < 4; mf++) {
#pragma unroll
        for (int half = 0; half < 2; half++) {
            int r = m0 + (wm << 6) + (mf << 4) + g + half * 8;
            if (r >= M) continue;
            float dv = (flags & GF_WRITEY) ? dinv[r] : 0.f;
#pragma unroll
            for (int nf = 0; nf < 4; nf++) {
                int c = (wn << 5) + (nf << 3) + 2 * t;
                float v0 = acc[mf][nf][half * 2 + 0];
                float v1 = acc[mf][nf][half * 2 + 1];
                if (bias) { v0 += __ldg(bias + c); v1 += __ldg(bias + c + 1); }
                if (flags & GF_RELU) { v0 = fmaxf(v0, 0.f); v1 = fmaxf(v1, 0.f); }
                *(float2*)(C + (size_t)r * H + c) = make_float2(v0, v1);
                if (flags & GF_WRITEY)
                    *(float2*)(Y + (size_t)r * H + c) = make_float2(dv * v0, dv * v1);
            }
        }
    }
}

// ---------------- GCN propagation ----------------
__global__ void k_spmv_ub(int dir, int write_yn) {
    const float4* __restrict__ y = (const float4*)(dir ? g_yb : g_ya);
    float4* yn = (float4*)(dir ? g_ya : g_yb);
    int w = (blockIdx.x * blockDim.x + threadIdx.x) >> 5;
    int lane = threadIdx.x & 31;
    if (w >= NN) return;
    int start = g_offall[w], d = g_degall[w];
    float4 s = make_float4(0.f, 0.f, 0.f, 0.f);
    int base = 0;
    for (; base + 32 <= d; base += 32) {
        int nb = g_adj[start + base + lane];
#pragma unroll
        for (int j = 0; j < 32; j++) {
            int nbj = __shfl_sync(0xffffffffu, nb, j);
            float4 v = y[(size_t)nbj * 32 + lane];
            s.x += v.x; s.y += v.y; s.z += v.z; s.w += v.w;
        }
    }
    int rem = d - base;
    if (rem) {
        int nb = (lane < rem) ? g_adj[start + base + lane] : 0;
#pragma unroll 4
        for (int j = 0; j < rem; j++) {
            int nbj = __shfl_sync(0xffffffffu, nb, j);
            float4 v = y[(size_t)nbj * 32 + lane];
            s.x += v.x; s.y += v.y; s.z += v.z; s.w += v.w;
        }
    }
    float di = g_dinv[w];
    size_t o = (size_t)w * 32 + lane;
    float4 aa = ((float4*)g_acc)[o];
    aa.x += di * s.x; aa.y += di * s.y; aa.z += di * s.z; aa.w += di * s.w;
    ((float4*)g_acc)[o] = aa;
    if (write_yn) {
        float dd = di * di;
        yn[o] = make_float4(dd * s.x, dd * s.y, dd * s.z, dd * s.w);
    }
}

// ---------------- SAGE mean aggregation ----------------
__global__ void k_spmv_bb(int dir) {
    const float4* __restrict__ h = (const float4*)(dir ? g_hb : g_ha);
    int w = (blockIdx.x * blockDim.x + threadIdx.x) >> 5;
    int lane = threadIdx.x & 31;
    if (w >= B_N) return;
    int start = g_offall[NN + w] - 2 * E_UB, d = g_degall[NN + w];
    float4 s = make_float4(0.f, 0.f, 0.f, 0.f);
    int base = 0;
    for (; base + 32 <= d; base += 32) {
        int nb = g_adjb[start + base + lane];
#pragma unroll
        for (int j = 0; j < 32; j++) {
            int nbj = __shfl_sync(0xffffffffu, nb, j);
            float4 v = h[(size_t)nbj * 32 + lane];
            s.x += v.x; s.y += v.y; s.z += v.z; s.w += v.w;
        }
    }
    int rem = d - base;
    if (rem) {
        int nb = (lane < rem) ? g_adjb[start + base + lane] : 0;
#pragma unroll 4
        for (int j = 0; j < rem; j++) {
            int nbj = __shfl_sync(0xffffffffu, nb, j);
            float4 v = h[(size_t)nbj * 32 + lane];
            s.x += v.x; s.y += v.y; s.z += v.z; s.w += v.w;
        }
    }
    float inv = 1.0f / (float)max(d, 1);
    ((float4*)g_agg)[(size_t)w * 32 + lane] =
        make_float4(inv * s.x, inv * s.y, inv * s.z, inv * s.w);
}

// ---------------- attention fusion ----------------
__global__ void k_fuse(const float* __restrict__ Wf2, const float* __restrict__ bf2) {
    int w = (blockIdx.x * blockDim.x + threadIdx.x) >> 5;
    int lane = threadIdx.x & 31;
    if (w >= B_N) return;
    size_t o = (size_t)w * 32 + lane;
    float4 r = ((const float4*)g_relu)[o];
    const float* w2 = Wf2 + 8 * lane;
    float z0 = r.x * w2[0] + r.y * w2[2] + r.z * w2[4] + r.w * w2[6];
    float z1 = r.x * w2[1] + r.y * w2[3] + r.z * w2[5] + r.w * w2[7];
#pragma unroll
    for (int s = 16; s > 0; s >>= 1) {
        z0 += __shfl_xor_sync(0xffffffffu, z0, s);
        z1 += __shfl_xor_sync(0xffffffffu, z1, s);
    }
    z0 += bf2[0]; z1 += bf2[1];
    float m = fmaxf(z0, z1);
    float e0 = expf(z0 - m), e1 = expf(z1 - m);
    float inv = 1.0f / (e0 + e1);
    float a0 = e0 * inv, a1 = e1 * inv;
    const float third = 1.0f / 3.0f;
    float4 cb = ((const float4*)g_acc)[(size_t)(U_N + w) * 32 + lane];  // unscaled acc
    cb.x *= third; cb.y *= third; cb.z *= third; cb.w *= third;
    float4 ct = ((const float4*)g_ha)[o];
    ((float4*)g_fused)[o] = make_float4(a0 * cb.x + a1 * ct.x,
                                        a0 * cb.y + a1 * ct.y,
                                        a0 * cb.z + a1 * ct.z,
                                        a0 * cb.w + a1 * ct.w);
}

// ---------------- final scoring ----------------
__global__ void k_score(const int* __restrict__ pu, const int* __restrict__ pb,
                        float* __restrict__ out) {
    int w = (blockIdx.x * blockDim.x + threadIdx.x) >> 5;
    int lane = threadIdx.x & 31;
    if (w >= P_N) return;
    int u = pu[w], b = pb[w];
    float4 a = ((const float4*)g_acc)[(size_t)u * 32 + lane];
    float4 f = ((const float4*)g_fused)[(size_t)b * 32 + lane];
    float s = a.x * f.x + a.y * f.y + a.z * f.z + a.w * f.w;
#pragma unroll
    for (int o = 16; o > 0; o >>= 1) s += __shfl_xor_sync(0xffffffffu, s, o);
    if (lane == 0) out[w] = s * (1.0f / 3.0f);
}

// ---------------- host ----------------
extern "C" void kernel_launch(void* const* d_in, const int* in_sizes, int n_in,
                              void* d_out, int out_size) {
    const float* user_x = (const float*)d_in[0];
    const float* book_x = (const float*)d_in[1];
    const int* ub_src = (const int*)d_in[2];
    const int* ub_dst = (const int*)d_in[3];
    const int* bb_src = (const int*)d_in[4];
    const int* bb_dst = (const int*)d_in[5];
    const int* pred_u = (const int*)d_in[6];
    const int* pred_b = (const int*)d_in[7];
    const float* Wu  = (const float*)d_in[8];
    const float* bu  = (const float*)d_in[9];
    const float* Wub = (const float*)d_in[10];
    const float* bub = (const float*)d_in[11];
    const float* Wbb = (const float*)d_in[12];
    const float* bbb = (const float*)d_in[13];
    const float* Wl1 = (const float*)d_in[14];
    const float* bl1 = (const float*)d_in[15];
    const float* Wr1 = (const float*)d_in[16];
    const float* Wl2 = (const float*)d_in[17];
    const float* bl2 = (const float*)d_in[18];
    const float* Wr2 = (const float*)d_in[19];
    const float* Wf1 = (const float*)d_in[20];
    const float* bf1 = (const float*)d_in[21];
    const float* Wf2 = (const float*)d_in[22];
    const float* bf2 = (const float*)d_in[23];
    float* out = (float*)d_out;

    void *p_acc, *p_ha, *p_hb, *p_agg, *p_relu, *p_deg, *p_off, *p_bs, *p_ya, *p_dinv;
    cudaGetSymbolAddress(&p_acc, g_acc);
    cudaGetSymbolAddress(&p_ha, g_ha);
    cudaGetSymbolAddress(&p_hb, g_hb);
    cudaGetSymbolAddress(&p_agg, g_agg);
    cudaGetSymbolAddress(&p_relu, g_relu);
    cudaGetSymbolAddress(&p_deg, g_degall);
    cudaGetSymbolAddress(&p_off, g_offall);
    cudaGetSymbolAddress(&p_bs, g_bsums);
    cudaGetSymbolAddress(&p_ya, g_ya);
    cudaGetSymbolAddress(&p_dinv, g_dinv);
    float* acc = (float*)p_acc;
    float* ha = (float*)p_ha;
    float* hb = (float*)p_hb;
    float* agg = (float*)p_agg;
    float* relu = (float*)p_relu;
    int* dg = (int*)p_deg;
    int* off = (int*)p_off;
    int* bs = (int*)p_bs;
    float* ya = (float*)p_ya;
    float* dinv = (float*)p_dinv;

    const int TB = 256;
    const int NB_A = (NA + TB - 1) / TB;
    const int NB_E = (E_UB + TB - 1) / TB;   // E_UB >= E_BB
    const int SCAN_A = (NA + 1023) / 1024;   // 196

    // --- graph structure build (6 launches) ---
    k_zero<<<NB_A, TB>>>();
    k_deg<<<NB_E, TB>>>(ub_src, ub_dst, bb_dst);
    k_blocksum<<<SCAN_A, 1024>>>(dg, NA, bs);
    k_scan_small<<<1, 1024>>>(bs, SCAN_A);
    k_scan_block<<<SCAN_A, 1024>>>(dg, NA, bs, off);
    k_fill<<<NB_E, TB>>>(ub_src, ub_dst, bb_src, bb_dst);

    // --- projections: x0 into g_acc, y0 = dinv*x0 into g_ya (fused) ---
    const int GU = (U_N + 127) / 128;
    const int GB = (B_N + 127) / 128;
    k_gemm_mma<<<GU, 256>>>(user_x, Wu, DU, 1.0f, nullptr, nullptr, 0,
                            bu, acc, U_N, GF_WRITEY, ya, dinv);
    k_gemm_mma<<<GB, 256>>>(book_x, Wub, DB, 1.0f, nullptr, nullptr, 0,
                            bub, acc + (size_t)U_N * H, B_N, GF_WRITEY,
                            ya + (size_t)U_N * H, dinv + U_N);

    // --- LightGCN: 2 rounds ---
    k_spmv_ub<<<(NN * 32 + TB - 1) / TB, TB>>>(0, 1);
    k_spmv_ub<<<(NN * 32 + TB - 1) / TB, TB>>>(1, 0);   // last round: skip yn write

    // --- SAGE over book-book graph (merged L+R GEMMs) ---
    const int NB_BW = (B_N * 32 + TB - 1) / TB;
    k_gemm_mma<<<GB, 256>>>(book_x, Wbb, DB, 1.0f, nullptr, nullptr, 0,
                            bbb, ha, B_N, 0, nullptr, nullptr);

    k_spmv_bb<<<NB_BW, TB>>>(0);
    k_gemm_mma<<<GB, 256>>>(agg, Wl1, H, 1.0f, ha, Wr1, H,
                            bl1, hb, B_N, GF_RELU, nullptr, nullptr);

    k_spmv_bb<<<NB_BW, TB>>>(1);
    k_gemm_mma<<<GB, 256>>>(agg, Wl2, H, 1.0f, hb, Wr2, H,
                            bl2, ha, B_N, GF_RELU, nullptr, nullptr);
    // book_content = ha

    // --- attention fusion: relu = relu([acc_b/3, content] @ Wf1 + bf1) (merged) ---
    k_gemm_mma<<<GB, 256>>>(acc + (size_t)U_N * H, Wf1, H, 1.0f / 3.0f,
                            ha, Wf1 + (size_t)H * H, H,
                            bf1, relu, B_N, GF_RELU, nullptr, nullptr);
    k_fuse<<<NB_BW, TB>>>(Wf2, bf2);

    // --- scoring ---
    k_score<<<(P_N * 32 + TB - 1) / TB, TB>>>(pred_u, pred_b, out);
}

// round 5
// speedup vs baseline: 1.6320x; 1.1449x over previous
#include <cuda_runtime.h>
#include <cuda_bf16.h>
#include <cstdint>
#include <math.h>

// Problem constants
#define U_N   100000
#define B_N   50000
#define NN    150000
#define NA    200000
#define E_UB  800000
#define E_BB  600000
#define P_N   400000
#define DU    64
#define DB    128
#define H     128

// weight k-offsets in transposed hi/lo store
#define WO_WU   0
#define WO_WUB  64
#define WO_WBB  192
#define WO_WL1  320
#define WO_WR1  448
#define WO_WL2  576
#define WO_WR2  704
#define WO_WF1A 832
#define WO_WF1B 960
#define WT_TOTK 1088

// ---------------- device scratch ----------------
__device__ int   g_degall[NA];
__device__ int   g_offall[NA];
__device__ int   g_cur[NN];
__device__ int   g_curb[B_N];
__device__ int   g_adj[2 * E_UB];
__device__ int   g_adjb[E_BB];
__device__ int   g_bsums[1024];
__device__ float g_dinv[NN];
__device__ float g_acc[(size_t)NN * H];
__device__ float g_ya[(size_t)NN * H];
__device__ float g_yb[(size_t)NN * H];
__device__ float g_ha[(size_t)B_N * H];
__device__ float g_hb[(size_t)B_N * H];
__device__ float g_agg[(size_t)B_N * H];
__device__ float g_relu[(size_t)B_N * H];
__device__ float g_fused[(size_t)B_N * H];
__device__ uint32_t g_wt_hi[WT_TOTK * 64];   // [seg][n][k/2] bf16x2 pairs, W^T layout
__device__ uint32_t g_wt_lo[WT_TOTK * 64];

__device__ __forceinline__ float ftrunc16(float x) {
    return __uint_as_float(__float_as_uint(x) & 0xFFFF0000u);
}
__device__ __forceinline__ uint32_t bf16x2_pack(float lo_elem, float hi_elem) {
    uint32_t r;
    asm("cvt.rn.bf16x2.f32 %0, %1, %2;" : "=r"(r) : "f"(hi_elem), "f"(lo_elem));
    return r;
}

// ---------------- init: zero counters + precompute weight hi/lo panels ----------------
__global__ void k_init(const float* __restrict__ Wu, const float* __restrict__ Wub,
                       const float* __restrict__ Wbb, const float* __restrict__ Wl1,
                       const float* __restrict__ Wr1, const float* __restrict__ Wl2,
                       const float* __restrict__ Wr2, const float* __restrict__ Wf1) {
    int i = blockIdx.x * blockDim.x + threadIdx.x;
    if (i < NA) g_degall[i] = 0;
    if (i < NN) g_cur[i] = 0;
    if (i < B_N) g_curb[i] = 0;
    if (i < WT_TOTK * 64) {
        const int offs[10] = {0, 64, 192, 320, 448, 576, 704, 832, 960, 1088};
        const float* Wp[9] = {Wu, Wub, Wbb, Wl1, Wr1, Wl2, Wr2, Wf1, Wf1 + 128 * 128};
        int e = i * 2;
        int s = 0;
        while (e >= offs[s + 1] * 128) s++;
        int Kw = offs[s + 1] - offs[s];
        int loc = e - offs[s] * 128;
        int n = loc / Kw, k = loc - n * Kw;
        const float* W = Wp[s];
        float a = W[(size_t)k * H + n];
        float b = W[(size_t)(k + 1) * H + n];
        g_wt_hi[i] = __byte_perm(__float_as_uint(a), __float_as_uint(b), 0x7632);
        g_wt_lo[i] = bf16x2_pack(a - ftrunc16(a), b - ftrunc16(b));
    }
}

// ---------------- graph build ----------------
__global__ void k_deg(const int* __restrict__ usrc, const int* __restrict__ udst,
                      const int* __restrict__ bdst) {
    int e = blockIdx.x * blockDim.x + threadIdx.x;
    if (e < E_UB) {
        atomicAdd(&g_degall[usrc[e]], 1);
        atomicAdd(&g_degall[U_N + udst[e]], 1);
    }
    if (e < E_BB) atomicAdd(&g_degall[NN + bdst[e]], 1);
}

__global__ void k_blocksum(const int* __restrict__ in, int n, int* __restrict__ bs) {
    __shared__ int sh[1024];
    int t = threadIdx.x, i = blockIdx.x * 1024 + t;
    sh[t] = (i < n) ? in[i] : 0;
    __syncthreads();
    for (int s = 512; s > 0; s >>= 1) {
        if (t < s) sh[t] += sh[t + s];
        __syncthreads();
    }
    if (t == 0) bs[blockIdx.x] = sh[0];
}

__global__ void k_scan_small(int* bs, int nb) {
    __shared__ int sh[1024];
    int t = threadIdx.x;
    sh[t] = (t < nb) ? bs[t] : 0;
    __syncthreads();
    for (int o = 1; o < 1024; o <<= 1) {
        int v = (t >= o) ? sh[t - o] : 0;
        __syncthreads();
        sh[t] += v;
        __syncthreads();
    }
    if (t < nb) bs[t] = t ? sh[t - 1] : 0;
}

__global__ void k_scan_block(const int* __restrict__ in, int n,
                             const int* __restrict__ bs, int* __restrict__ out) {
    __shared__ int sh[1024];
    int t = threadIdx.x, i = blockIdx.x * 1024 + t;
    int d = (i < n) ? in[i] : 0;
    sh[t] = d;
    __syncthreads();
    for (int o = 1; o < 1024; o <<= 1) {
        int v = (t >= o) ? sh[t - o] : 0;
        __syncthreads();
        sh[t] += v;
        __syncthreads();
    }
    if (i < n) {
        out[i] = (t ? sh[t - 1] : 0) + bs[blockIdx.x];
        if (i < NN) g_dinv[i] = (d > 0) ? rsqrtf((float)d) : 0.0f;
    }
}

__global__ void k_fill(const int* __restrict__ usrc, const int* __restrict__ udst,
                       const int* __restrict__ bsrc, const int* __restrict__ bdst) {
    int e = blockIdx.x * blockDim.x + threadIdx.x;
    if (e < E_UB) {
        int u = usrc[e], b = U_N + udst[e];
        int p = atomicAdd(&g_cur[u], 1);
        g_adj[g_offall[u] + p] = b;
        int q = atomicAdd(&g_cur[b], 1);
        g_adj[g_offall[b] + q] = u;
    }
    if (e < E_BB) {
        int d = bdst[e];
        int p = atomicAdd(&g_curb[d], 1);
        g_adjb[g_offall[NN + d] - 2 * E_UB + p] = bsrc[e];
    }
}

// ---------------- bf16 split-3 HMMA GEMM core ----------------
#define GF_RELU   2
#define GF_WRITEY 4

#define MMA_BF16(d, a, b) \
    asm volatile("mma.sync.aligned.m16n8k16.row.col.f32.bf16.bf16.f32 " \
                 "{%0,%1,%2,%3}, {%4,%5,%6,%7}, {%8,%9}, {%0,%1,%2,%3};" \
                 : "+f"((d)[0]), "+f"((d)[1]), "+f"((d)[2]), "+f"((d)[3]) \
                 : "r"((a)[0]), "r"((a)[1]), "r"((a)[2]), "r"((a)[3]), \
                   "r"((b)[0]), "r"((b)[1]))

struct SmemT {
    __nv_bfloat16 Ah[128][36];
    __nv_bfloat16 Al[128][36];
    __nv_bfloat16 Bh[128][34];
    __nv_bfloat16 Bl[128][34];
};

__device__ __forceinline__ void gemm_body(
    SmemT& sm, int mblk,
    const float* __restrict__ A1, int wo1, int K1, float s1,
    const float* __restrict__ A2, int wo2, int K2,
    const float* __restrict__ bias, float* __restrict__ C, int M, int flags,
    float* __restrict__ Y, const float* __restrict__ dinv) {
    const int tid = threadIdx.x;
    const int lane = tid & 31, wid = tid >> 5;
    const int g = lane >> 2, t = lane & 3;
    const int wm = wid >> 2, wn = wid & 3;
    const int m0 = mblk * 128;
    const int np1 = K1 >> 5, np = np1 + (K2 >> 5);

    float acc[4][4][4];
#pragma unroll
    for (int i = 0; i < 4; i++)
#pragma unroll
        for (int j = 0; j < 4; j++) {
            acc[i][j][0] = 0.f; acc[i][j][1] = 0.f;
            acc[i][j][2] = 0.f; acc[i][j][3] = 0.f;
        }

    int arow[4], ac4[4];
#pragma unroll
    for (int i = 0; i < 4; i++) {
        int idx = tid + (i << 8);
        arow[i] = idx >> 3;
        ac4[i] = (idx & 7) << 2;
    }
    const int bn0 = (tid * 2) >> 2, bg0 = (tid * 2) & 3;
    const int bn1 = (tid * 2 + 1) >> 2, bg1 = (tid * 2 + 1) & 3;

    float4 av[4];
    float scs;
    {
        const float* Ap = np1 ? A1 : A2;
        int Ks = np1 ? K1 : K2;
        scs = np1 ? s1 : 1.0f;
#pragma unroll
        for (int i = 0; i < 4; i++) {
            int m = m0 + arow[i];
            av[i] = make_float4(0.f, 0.f, 0.f, 0.f);
            if (m < M) av[i] = *(const float4*)(Ap + (size_t)m * Ks + ac4[i]);
        }
    }

    for (int p = 0; p < np; p++) {
        int wo, Kw, kl;
        if (p < np1) { wo = wo1; Kw = K1; kl = p << 5; }
        else         { wo = wo2; Kw = K2; kl = (p - np1) << 5; }

        // B loads (precomputed W^T hi/lo panels, L2-hot) — issue early
        const uint32_t* bhp = g_wt_hi + wo * 64;
        const uint32_t* blp = g_wt_lo + wo * 64;
        int bi0 = ((bn0 * Kw + kl) >> 1) + bg0 * 4;
        int bi1 = ((bn1 * Kw + kl) >> 1) + bg1 * 4;
        uint4 BH0 = *(const uint4*)(bhp + bi0);
        uint4 BH1 = *(const uint4*)(bhp + bi1);
        uint4 BL0 = *(const uint4*)(blp + bi0);
        uint4 BL1 = *(const uint4*)(blp + bi1);

        // A fast-split stores (from prefetched registers)
#pragma unroll
        for (int i = 0; i < 4; i++) {
            float x0 = scs * av[i].x, x1 = scs * av[i].y;
            float x2 = scs * av[i].z, x3 = scs * av[i].w;
            uint32_t hp0 = __byte_perm(__float_as_uint(x0), __float_as_uint(x1), 0x7632);
            uint32_t hp1 = __byte_perm(__float_as_uint(x2), __float_as_uint(x3), 0x7632);
            uint32_t lp0 = bf16x2_pack(x0 - ftrunc16(x0), x1 - ftrunc16(x1));
            uint32_t lp1 = bf16x2_pack(x2 - ftrunc16(x2), x3 - ftrunc16(x3));
            *(uint32_t*)&sm.Ah[arow[i]][ac4[i]]     = hp0;
            *(uint32_t*)&sm.Ah[arow[i]][ac4[i] + 2] = hp1;
            *(uint32_t*)&sm.Al[arow[i]][ac4[i]]     = lp0;
            *(uint32_t*)&sm.Al[arow[i]][ac4[i] + 2] = lp1;
        }
        // B stores
        *(uint32_t*)&sm.Bh[bn0][bg0 * 8 + 0] = BH0.x;
        *(uint32_t*)&sm.Bh[bn0][bg0 * 8 + 2] = BH0.y;
        *(uint32_t*)&sm.Bh[bn0][bg0 * 8 + 4] = BH0.z;
        *(uint32_t*)&sm.Bh[bn0][bg0 * 8 + 6] = BH0.w;
        *(uint32_t*)&sm.Bh[bn1][bg1 * 8 + 0] = BH1.x;
        *(uint32_t*)&sm.Bh[bn1][bg1 * 8 + 2] = BH1.y;
        *(uint32_t*)&sm.Bh[bn1][bg1 * 8 + 4] = BH1.z;
        *(uint32_t*)&sm.Bh[bn1][bg1 * 8 + 6] = BH1.w;
        *(uint32_t*)&sm.Bl[bn0][bg0 * 8 + 0] = BL0.x;
        *(uint32_t*)&sm.Bl[bn0][bg0 * 8 + 2] = BL0.y;
        *(uint32_t*)&sm.Bl[bn0][bg0 * 8 + 4] = BL0.z;
        *(uint32_t*)&sm.Bl[bn0][bg0 * 8 + 6] = BL0.w;
        *(uint32_t*)&sm.Bl[bn1][bg1 * 8 + 0] = BL1.x;
        *(uint32_t*)&sm.Bl[bn1][bg1 * 8 + 2] = BL1.y;
        *(uint32_t*)&sm.Bl[bn1][bg1 * 8 + 4] = BL1.z;
        *(uint32_t*)&sm.Bl[bn1][bg1 * 8 + 6] = BL1.w;
        __syncthreads();

        // prefetch next A tile (overlaps MMA)
        float nsc = scs;
        if (p + 1 < np) {
            int q = p + 1;
            const float* Ap; int Ks, kl2;
            if (q < np1) { Ap = A1; Ks = K1; kl2 = q << 5; nsc = s1; }
            else         { Ap = A2; Ks = K2; kl2 = (q - np1) << 5; nsc = 1.0f; }
#pragma unroll
            for (int i = 0; i < 4; i++) {
                int m = m0 + arow[i];
                av[i] = make_float4(0.f, 0.f, 0.f, 0.f);
                if (m < M) av[i] = *(const float4*)(Ap + (size_t)m * Ks + kl2 + ac4[i]);
            }
        }

#pragma unroll
        for (int ks = 0; ks < 2; ks++) {
            const int kk = (ks << 4) + 2 * t;
            uint32_t bh[4][2], bl[4][2];
#pragma unroll
            for (int nf = 0; nf < 4; nf++) {
                int n = (wn << 5) + (nf << 3) + g;
                bh[nf][0] = *(const uint32_t*)&sm.Bh[n][kk];
                bh[nf][1] = *(const uint32_t*)&sm.Bh[n][kk + 8];
                bl[nf][0] = *(const uint32_t*)&sm.Bl[n][kk];
                bl[nf][1] = *(const uint32_t*)&sm.Bl[n][kk + 8];
            }
#pragma unroll
            for (int mf = 0; mf < 4; mf++) {
                int r = (wm << 6) + (mf << 4) + g;
                uint32_t ah[4], al[4];
                ah[0] = *(const uint32_t*)&sm.Ah[r][kk];
                ah[1] = *(const uint32_t*)&sm.Ah[r + 8][kk];
                ah[2] = *(const uint32_t*)&sm.Ah[r][kk + 8];
                ah[3] = *(const uint32_t*)&sm.Ah[r + 8][kk + 8];
                al[0] = *(const uint32_t*)&sm.Al[r][kk];
                al[1] = *(const uint32_t*)&sm.Al[r + 8][kk];
                al[2] = *(const uint32_t*)&sm.Al[r][kk + 8];
                al[3] = *(const uint32_t*)&sm.Al[r + 8][kk + 8];
#pragma unroll
                for (int nf = 0; nf < 4; nf++) {
                    MMA_BF16(acc[mf][nf], ah, bh[nf]);
                    MMA_BF16(acc[mf][nf], ah, bl[nf]);
                    MMA_BF16(acc[mf][nf], al, bh[nf]);
                }
            }
        }
        __syncthreads();
        scs = nsc;
    }

    // epilogue
#pragma unroll
    for (int mf = 0; mf < 4; mf++) {
#pragma unroll
        for (int half = 0; half < 2; half++) {
            int r = m0 + (wm << 6) + (mf << 4) + g + half * 8;
            if (r >= M) continue;
            float dv = (flags & GF_WRITEY) ? dinv[r] : 0.f;
#pragma unroll
            for (int nf = 0; nf < 4; nf++) {
                int c = (wn << 5) + (nf << 3) + 2 * t;
                float v0 = acc[mf][nf][half * 2 + 0];
                float v1 = acc[mf][nf][half * 2 + 1];
                if (bias) { v0 += __ldg(bias + c); v1 += __ldg(bias + c + 1); }
                if (flags & GF_RELU) { v0 = fmaxf(v0, 0.f); v1 = fmaxf(v1, 0.f); }
                *(float2*)(C + (size_t)r * H + c) = make_float2(v0, v1);
                if (flags & GF_WRITEY)
                    *(float2*)(Y + (size_t)r * H + c) = make_float2(dv * v0, dv * v1);
            }
        }
    }
}

// batched projections: user-proj | book-proj | book-content-proj
#define GU_BLKS 782   // ceil(100000/128)
#define GB_BLKS 391   // ceil(50000/128)

__global__ __launch_bounds__(256)
void k_gemm3(const float* __restrict__ user_x, const float* __restrict__ book_x,
             const float* __restrict__ bu, const float* __restrict__ bub,
             const float* __restrict__ bbb) {
    __shared__ SmemT sm;
    int b = blockIdx.x;
    const float* A; const float* bi; float* Cp; float* Yp; const float* dv;
    int wo, K, M, fl, mblk;
    if (b < GU_BLKS) {
        mblk = b; A = user_x; wo = WO_WU; K = DU; M = U_N; bi = bu;
        Cp = g_acc; fl = GF_WRITEY; Yp = g_ya; dv = g_dinv;
    } else if (b < GU_BLKS + GB_BLKS) {
        mblk = b - GU_BLKS; A = book_x; wo = WO_WUB; K = DB; M = B_N; bi = bub;
        Cp = g_acc + (size_t)U_N * H; fl = GF_WRITEY;
        Yp = g_ya + (size_t)U_N * H; dv = g_dinv + U_N;
    } else {
        mblk = b - GU_BLKS - GB_BLKS; A = book_x; wo = WO_WBB; K = DB; M = B_N;
        bi = bbb; Cp = g_ha; fl = 0; Yp = nullptr; dv = nullptr;
    }
    gemm_body(sm, mblk, A, wo, K, 1.0f, nullptr, 0, 0, bi, Cp, M, fl, Yp, dv);
}

__global__ __launch_bounds__(256)
void k_gemm1(const float* __restrict__ A1, int wo1, int K1, float s1,
             const float* __restrict__ A2, int wo2, int K2,
             const float* __restrict__ bias, float* __restrict__ C,
             int M, int flags) {
    __shared__ SmemT sm;
    gemm_body(sm, blockIdx.x, A1, wo1, K1, s1, A2, wo2, K2, bias, C, M, flags,
              nullptr, nullptr);
}

// ---------------- merged SpMV: LightGCN (warps [0,NN)) + SAGE agg (warps [NN,NN+B_N)) ----
__global__ void k_spmv(const float4* __restrict__ yin, float4* __restrict__ yout,
                       int write_yn, const float4* __restrict__ hin) {
    int w = (blockIdx.x * blockDim.x + threadIdx.x) >> 5;
    int lane = threadIdx.x & 31;
    if (w < NN) {
        int start = g_offall[w], d = g_degall[w];
        float4 s = make_float4(0.f, 0.f, 0.f, 0.f);
        int base = 0;
        for (; base + 32 <= d; base += 32) {
            int nb = g_adj[start + base + lane];
#pragma unroll
            for (int j = 0; j < 32; j++) {
                int nbj = __shfl_sync(0xffffffffu, nb, j);
                float4 v = yin[(size_t)nbj * 32 + lane];
                s.x += v.x; s.y += v.y; s.z += v.z; s.w += v.w;
            }
        }
        int rem = d - base;
        if (rem) {
            int nb = (lane < rem) ? g_adj[start + base + lane] : 0;
#pragma unroll 4
            for (int j = 0; j < rem; j++) {
                int nbj = __shfl_sync(0xffffffffu, nb, j);
                float4 v = yin[(size_t)nbj * 32 + lane];
                s.x += v.x; s.y += v.y; s.z += v.z; s.w += v.w;
            }
        }
        float di = g_dinv[w];
        size_t o = (size_t)w * 32 + lane;
        float4 aa = ((float4*)g_acc)[o];
        aa.x += di * s.x; aa.y += di * s.y; aa.z += di * s.z; aa.w += di * s.w;
        ((float4*)g_acc)[o] = aa;
        if (write_yn) {
            float dd = di * di;
            yout[o] = make_float4(dd * s.x, dd * s.y, dd * s.z, dd * s.w);
        }
    } else if (w < NN + B_N) {
        int wb = w - NN;
        int start = g_offall[NN + wb] - 2 * E_UB, d = g_degall[NN + wb];
        float4 s = make_float4(0.f, 0.f, 0.f, 0.f);
        int base = 0;
        for (; base + 32 <= d; base += 32) {
            int nb = g_adjb[start + base + lane];
#pragma unroll
            for (int j = 0; j < 32; j++) {
                int nbj = __shfl_sync(0xffffffffu, nb, j);
                float4 v = hin[(size_t)nbj * 32 + lane];
                s.x += v.x; s.y += v.y; s.z += v.z; s.w += v.w;
            }
        }
        int rem = d - base;
        if (rem) {
            int nb = (lane < rem) ? g_adjb[start + base + lane] : 0;
#pragma unroll 4
            for (int j = 0; j < rem; j++) {
                int nbj = __shfl_sync(0xffffffffu, nb, j);
                float4 v = hin[(size_t)nbj * 32 + lane];
                s.x += v.x; s.y += v.y; s.z += v.z; s.w += v.w;
            }
        }
        float inv = 1.0f / (float)max(d, 1);
        ((float4*)g_agg)[(size_t)wb * 32 + lane] =
            make_float4(inv * s.x, inv * s.y, inv * s.z, inv * s.w);
    }
}

// ---------------- attention fusion ----------------
__global__ void k_fuse(const float* __restrict__ Wf2, const float* __restrict__ bf2) {
    int w = (blockIdx.x * blockDim.x + threadIdx.x) >> 5;
    int lane = threadIdx.x & 31;
    if (w >= B_N) return;
    size_t o = (size_t)w * 32 + lane;
    float4 r = ((const float4*)g_relu)[o];
    const float* w2 = Wf2 + 8 * lane;
    float z0 = r.x * w2[0] + r.y * w2[2] + r.z * w2[4] + r.w * w2[6];
    float z1 = r.x * w2[1] + r.y * w2[3] + r.z * w2[5] + r.w * w2[7];
#pragma unroll
    for (int s = 16; s > 0; s >>= 1) {
        z0 += __shfl_xor_sync(0xffffffffu, z0, s);
        z1 += __shfl_xor_sync(0xffffffffu, z1, s);
    }
    z0 += bf2[0]; z1 += bf2[1];
    float m = fmaxf(z0, z1);
    float e0 = expf(z0 - m), e1 = expf(z1 - m);
    float inv = 1.0f / (e0 + e1);
    float a0 = e0 * inv, a1 = e1 * inv;
    const float third = 1.0f / 3.0f;
    float4 cb = ((const float4*)g_acc)[(size_t)(U_N + w) * 32 + lane];
    cb.x *= third; cb.y *= third; cb.z *= third; cb.w *= third;
    float4 ct = ((const float4*)g_ha)[o];
    ((float4*)g_fused)[o] = make_float4(a0 * cb.x + a1 * ct.x,
                                        a0 * cb.y + a1 * ct.y,
                                        a0 * cb.z + a1 * ct.z,
                                        a0 * cb.w + a1 * ct.w);
}

// ---------------- final scoring ----------------
__global__ void k_score(const int* __restrict__ pu, const int* __restrict__ pb,
                        float* __restrict__ out) {
    int w = (blockIdx.x * blockDim.x + threadIdx.x) >> 5;
    int lane = threadIdx.x & 31;
    if (w >= P_N) return;
    int u = pu[w], b = pb[w];
    float4 a = ((const float4*)g_acc)[(size_t)u * 32 + lane];
    float4 f = ((const float4*)g_fused)[(size_t)b * 32 + lane];
    float s = a.x * f.x + a.y * f.y + a.z * f.z + a.w * f.w;
#pragma unroll
    for (int o = 16; o > 0; o >>= 1) s += __shfl_xor_sync(0xffffffffu, s, o);
    if (lane == 0) out[w] = s * (1.0f / 3.0f);
}

// ---------------- host ----------------
extern "C" void kernel_launch(void* const* d_in, const int* in_sizes, int n_in,
                              void* d_out, int out_size) {
    const float* user_x = (const float*)d_in[0];
    const float* book_x = (const float*)d_in[1];
    const int* ub_src = (const int*)d_in[2];
    const int* ub_dst = (const int*)d_in[3];
    const int* bb_src = (const int*)d_in[4];
    const int* bb_dst = (const int*)d_in[5];
    const int* pred_u = (const int*)d_in[6];
    const int* pred_b = (const int*)d_in[7];
    const float* Wu  = (const float*)d_in[8];
    const float* bu  = (const float*)d_in[9];
    const float* Wub = (const float*)d_in[10];
    const float* bub = (const float*)d_in[11];
    const float* Wbb = (const float*)d_in[12];
    const float* bbb = (const float*)d_in[13];
    const float* Wl1 = (const float*)d_in[14];
    const float* bl1 = (const float*)d_in[15];
    const float* Wr1 = (const float*)d_in[16];
    const float* Wl2 = (const float*)d_in[17];
    const float* bl2 = (const float*)d_in[18];
    const float* Wr2 = (const float*)d_in[19];
    const float* Wf1 = (const float*)d_in[20];
    const float* bf1 = (const float*)d_in[21];
    const float* Wf2 = (const float*)d_in[22];
    const float* bf2 = (const float*)d_in[23];
    float* out = (float*)d_out;

    void *p_acc, *p_ha, *p_hb, *p_agg, *p_relu, *p_deg, *p_off, *p_bs, *p_ya, *p_yb;
    cudaGetSymbolAddress(&p_acc, g_acc);
    cudaGetSymbolAddress(&p_ha, g_ha);
    cudaGetSymbolAddress(&p_hb, g_hb);
    cudaGetSymbolAddress(&p_agg, g_agg);
    cudaGetSymbolAddress(&p_relu, g_relu);
    cudaGetSymbolAddress(&p_deg, g_degall);
    cudaGetSymbolAddress(&p_off, g_offall);
    cudaGetSymbolAddress(&p_bs, g_bsums);
    cudaGetSymbolAddress(&p_ya, g_ya);
    cudaGetSymbolAddress(&p_yb, g_yb);
    float* acc = (float*)p_acc;
    float* ha = (float*)p_ha;
    float* hb = (float*)p_hb;
    float* agg = (float*)p_agg;
    float* relu = (float*)p_relu;
    int* dg = (int*)p_deg;
    int* off = (int*)p_off;
    int* bs = (int*)p_bs;
    float4* ya4 = (float4*)p_ya;
    float4* yb4 = (float4*)p_yb;
    float4* ha4 = (float4*)p_ha;
    float4* hb4 = (float4*)p_hb;

    const int TB = 256;
    const int NB_A = (NA + TB - 1) / TB;           // 782, also covers weight prep
    const int NB_E = (E_UB + TB - 1) / TB;
    const int SCAN_A = (NA + 1023) / 1024;

    // --- init (zero + weight hi/lo precompute) + graph build ---
    k_init<<<NB_A, TB>>>(Wu, Wub, Wbb, Wl1, Wr1, Wl2, Wr2, Wf1);
    k_deg<<<NB_E, TB>>>(ub_src, ub_dst, bb_dst);
    k_blocksum<<<SCAN_A, 1024>>>(dg, NA, bs);
    k_scan_small<<<1, 1024>>>(bs, SCAN_A);
    k_scan_block<<<SCAN_A, 1024>>>(dg, NA, bs, off);
    k_fill<<<NB_E, TB>>>(ub_src, ub_dst, bb_src, bb_dst);

    // --- all three projections in one launch ---
    k_gemm3<<<GU_BLKS + 2 * GB_BLKS, 256>>>(user_x, book_x, bu, bub, bbb);

    // --- spmv round 0: LightGCN hop1 + SAGE agg from ha ---
    const int SPMV_BLKS = ((NN + B_N) * 32 + TB - 1) / TB;
    k_spmv<<<SPMV_BLKS, TB>>>(ya4, yb4, 1, ha4);

    // --- SAGE layer 1 (merged L+R) ---
    k_gemm1<<<GB_BLKS, 256>>>(agg, WO_WL1, H, 1.0f, ha, WO_WR1, H,
                              bl1, hb, B_N, GF_RELU);

    // --- spmv round 1: LightGCN hop2 (no yn write) + SAGE agg from hb ---
    k_spmv<<<SPMV_BLKS, TB>>>(yb4, ya4, 0, hb4);

    // --- SAGE layer 2 ---
    k_gemm1<<<GB_BLKS, 256>>>(agg, WO_WL2, H, 1.0f, hb, WO_WR2, H,
                              bl2, ha, B_N, GF_RELU);

    // --- attention fusion GEMM (merged halves; 1/3 folded into s1) ---
    k_gemm1<<<GB_BLKS, 256>>>(acc + (size_t)U_N * H, WO_WF1A, H, 1.0f / 3.0f,
                              ha, WO_WF1B, H, bf1, relu, B_N, GF_RELU);
    k_fuse<<<(B_N * 32 + TB - 1) / TB, TB>>>(Wf2, bf2);

    // --- scoring ---
    k_score<<<(P_N * 32 + TB - 1) / TB, TB>>>(pred_u, pred_b, out);
}